// round 9
// baseline (speedup 1.0000x reference)
#include <cuda_runtime.h>
#include <cstdint>

// Input:  x  (4, 64, 512, 512) fp32  -> flatten (BC=256, 512, 512)
// Output: [ll | lh | hl | hh], each (256, 256, 256) fp32, concatenated.
//
// FINAL. Single-level 2x2 Haar DWT, pure streaming kernel.
// Each thread: one float4 from row 2h and row 2h+1 (two 2x2 blocks),
// one float2 store into each of the 4 output planes. Exact grid, pow2
// index math, default cache policy (best measured kernel time; .cs hints
// were neutral-to-noise).
//
// Roofline status: 512 MiB total traffic (algorithmic minimum, fully
// coalesced) at the sm_103a path-independent LTS/HBM streaming cap
// (~6.3-6.5 TB/s run-to-run). ILP, store burst shaping, cache policy,
// smem staging, persistent grids: all measured non-binding.

static constexpr int BC    = 256;          // 4 * 64
static constexpr int W_IN  = 512;
static constexpr int H_OUT = 256;
static constexpr int W_OUT = 256;
static constexpr int PLANE = BC * H_OUT * W_OUT;        // 16,777,216 elems/plane
static constexpr int W4    = W_IN / 4;                  // 128 float4 per input row
static constexpr long long TOTAL_PAIRS = (long long)BC * H_OUT * (W_OUT / 2); // 8,388,608

__global__ void __launch_bounds__(256) fast_dwt_kernel(
    const float4* __restrict__ x,
    float* __restrict__ out)
{
    // Exact grid: no bounds check needed.
    unsigned idx = blockIdx.x * blockDim.x + threadIdx.x;   // < 8,388,608

    unsigned wq = idx & (W4 - 1);          // quad within row (W4=128, pow2)
    unsigned t  = idx >> 7;
    unsigned ho = t & (H_OUT - 1);         // 256, pow2
    unsigned bc = t >> 8;

    // Input rows 2*ho and 2*ho+1, as float4 indices.
    unsigned row0 = (bc * 512u + 2u * ho) * W4;
    float4 r0 = x[row0 + wq];
    float4 r1 = x[row0 + W4 + wq];

    float2 ll, lh, hl, hh;
    {
        float apb = r0.x + r0.y, amb = r0.x - r0.y;
        float cpd = r1.x + r1.y, cmd = r1.x - r1.y;
        ll.x = (apb + cpd) * 0.5f;  lh.x = (apb - cpd) * 0.5f;
        hl.x = (amb + cmd) * 0.5f;  hh.x = (amb - cmd) * 0.5f;
    }
    {
        float apb = r0.z + r0.w, amb = r0.z - r0.w;
        float cpd = r1.z + r1.w, cmd = r1.z - r1.w;
        ll.y = (apb + cpd) * 0.5f;  lh.y = (apb - cpd) * 0.5f;
        hl.y = (amb + cmd) * 0.5f;  hh.y = (amb - cmd) * 0.5f;
    }

    // Output offset within a plane (floats): (bc, ho, 2*wq)
    unsigned o = (bc * H_OUT + ho) * W_OUT + 2u * wq;
    *(float2*)(out + 0u * PLANE + o) = ll;
    *(float2*)(out + 1u * PLANE + o) = lh;
    *(float2*)(out + 2u * PLANE + o) = hl;
    *(float2*)(out + 3u * PLANE + o) = hh;
}

extern "C" void kernel_launch(void* const* d_in, const int* in_sizes, int n_in,
                              void* d_out, int out_size)
{
    const float4* x = (const float4*)d_in[0];
    float* out = (float*)d_out;

    const int threads = 256;
    const int blocks = (int)(TOTAL_PAIRS / threads);   // 32768, exact
    fast_dwt_kernel<<<blocks, threads>>>(x, out);
}

// round 10
// speedup vs baseline: 1.0008x; 1.0008x over previous
#include <cuda_runtime.h>
#include <cstdint>

// Input:  x  (4, 64, 512, 512) fp32  -> flatten (BC=256, 512, 512)
// Output: [ll | lh | hl | hh], each (256, 256, 256) fp32, concatenated.
//
// FINAL shape (thin threads, exact grid, pow2 index math, streaming-store
// hints), block size 512 (last untested tuning cell). Each thread reads one
// float4 from rows 2h and 2h+1 (two 2x2 Haar blocks) and writes a float2
// into each of the 4 output planes.
//
// Roofline status: 512 MiB total traffic (algorithmic minimum, fully
// coalesced) at the sm_103a path-independent LTS/HBM streaming cap
// (~6.3-6.5 TB/s run-to-run). ILP, burst shaping, cache policy, smem
// staging, persistent grids: all measured non-binding over 9 rounds.

static constexpr int BC    = 256;          // 4 * 64
static constexpr int W_IN  = 512;
static constexpr int H_OUT = 256;
static constexpr int W_OUT = 256;
static constexpr int PLANE = BC * H_OUT * W_OUT;        // 16,777,216 elems/plane
static constexpr int W4    = W_IN / 4;                  // 128 float4 per input row
static constexpr long long TOTAL_PAIRS = (long long)BC * H_OUT * (W_OUT / 2); // 8,388,608
static constexpr int THREADS = 512;

__device__ __forceinline__ float4 ldcs4(const float4* p) {
    float4 v;
    asm volatile("ld.global.cs.v4.f32 {%0,%1,%2,%3}, [%4];"
                 : "=f"(v.x), "=f"(v.y), "=f"(v.z), "=f"(v.w) : "l"(p));
    return v;
}

__device__ __forceinline__ void stcs2(float* p, float2 v) {
    asm volatile("st.global.cs.v2.f32 [%0], {%1,%2};"
                 :: "l"(p), "f"(v.x), "f"(v.y) : "memory");
}

__global__ void __launch_bounds__(THREADS) fast_dwt_kernel(
    const float4* __restrict__ x,
    float* __restrict__ out)
{
    // Exact grid: no bounds check needed.
    unsigned idx = blockIdx.x * blockDim.x + threadIdx.x;   // < 8,388,608

    unsigned wq = idx & (W4 - 1);          // quad within row (W4=128, pow2)
    unsigned t  = idx >> 7;
    unsigned ho = t & (H_OUT - 1);         // 256, pow2
    unsigned bc = t >> 8;

    // Input rows 2*ho and 2*ho+1, as float4 indices.
    unsigned row0 = (bc * 512u + 2u * ho) * W4;
    float4 r0 = ldcs4(x + row0 + wq);
    float4 r1 = ldcs4(x + row0 + W4 + wq);

    float2 ll, lh, hl, hh;
    {
        float apb = r0.x + r0.y, amb = r0.x - r0.y;
        float cpd = r1.x + r1.y, cmd = r1.x - r1.y;
        ll.x = (apb + cpd) * 0.5f;  lh.x = (apb - cpd) * 0.5f;
        hl.x = (amb + cmd) * 0.5f;  hh.x = (amb - cmd) * 0.5f;
    }
    {
        float apb = r0.z + r0.w, amb = r0.z - r0.w;
        float cpd = r1.z + r1.w, cmd = r1.z - r1.w;
        ll.y = (apb + cpd) * 0.5f;  lh.y = (apb - cpd) * 0.5f;
        hl.y = (amb + cmd) * 0.5f;  hh.y = (amb - cmd) * 0.5f;
    }

    // Output offset within a plane (floats): (bc, ho, 2*wq)
    unsigned o = (bc * H_OUT + ho) * W_OUT + 2u * wq;
    stcs2(out + 0u * PLANE + o, ll);
    stcs2(out + 1u * PLANE + o, lh);
    stcs2(out + 2u * PLANE + o, hl);
    stcs2(out + 3u * PLANE + o, hh);
}

extern "C" void kernel_launch(void* const* d_in, const int* in_sizes, int n_in,
                              void* d_out, int out_size)
{
    const float4* x = (const float4*)d_in[0];
    float* out = (float*)d_out;

    const int blocks = (int)(TOTAL_PAIRS / THREADS);   // 16384, exact
    fast_dwt_kernel<<<blocks, THREADS>>>(x, out);
}

// round 11
// speedup vs baseline: 1.0020x; 1.0012x over previous
#include <cuda_runtime.h>
#include <cstdint>

// Input:  x  (4, 64, 512, 512) fp32  -> flatten (BC=256, 512, 512)
// Output: [ll | lh | hl | hh], each (256, 256, 256) fp32, concatenated.
//
// SESSION FINAL (R3 configuration — best recorded bench, 81.0 us).
// Single-level 2x2 Haar DWT, pure streaming kernel. Each thread reads one
// float4 from rows 2h and 2h+1 (two 2x2 blocks) and writes a float2 into
// each of the 4 output planes. Streaming cache hints both directions,
// exact grid (no tail branch), power-of-two index math, 256 thr/CTA.
//
// Roofline status (10 rounds, 7 structural/tuning variants, 3 repeats):
//   512 MiB total traffic — algorithmic minimum, fully coalesced.
//   Pinned at the sm_103a path-independent LTS/HBM streaming cap
//   (~6.3-6.5 TB/s run-to-run DVFS wander). ILP, store burst shaping,
//   cache policy, smem staging, persistent grids, block size: all
//   measured non-binding. Kernel ~75-77 us; bench 81-82 us.

static constexpr int BC    = 256;          // 4 * 64
static constexpr int W_IN  = 512;
static constexpr int H_OUT = 256;
static constexpr int W_OUT = 256;
static constexpr int PLANE = BC * H_OUT * W_OUT;        // 16,777,216 elems/plane
static constexpr int W4    = W_IN / 4;                  // 128 float4 per input row
static constexpr long long TOTAL_PAIRS = (long long)BC * H_OUT * (W_OUT / 2); // 8,388,608

__device__ __forceinline__ float4 ldcs4(const float4* p) {
    float4 v;
    asm volatile("ld.global.cs.v4.f32 {%0,%1,%2,%3}, [%4];"
                 : "=f"(v.x), "=f"(v.y), "=f"(v.z), "=f"(v.w) : "l"(p));
    return v;
}

__device__ __forceinline__ void stcs2(float* p, float2 v) {
    asm volatile("st.global.cs.v2.f32 [%0], {%1,%2};"
                 :: "l"(p), "f"(v.x), "f"(v.y) : "memory");
}

__global__ void __launch_bounds__(256) fast_dwt_kernel(
    const float4* __restrict__ x,
    float* __restrict__ out)
{
    // Exact grid: no bounds check needed.
    unsigned idx = blockIdx.x * blockDim.x + threadIdx.x;   // < 8,388,608

    unsigned wq = idx & (W4 - 1);          // quad within row (W4=128, pow2)
    unsigned t  = idx >> 7;
    unsigned ho = t & (H_OUT - 1);         // 256, pow2
    unsigned bc = t >> 8;

    // Input rows 2*ho and 2*ho+1, as float4 indices.
    unsigned row0 = (bc * 512u + 2u * ho) * W4;
    float4 r0 = ldcs4(x + row0 + wq);
    float4 r1 = ldcs4(x + row0 + W4 + wq);

    float2 ll, lh, hl, hh;
    {
        float apb = r0.x + r0.y, amb = r0.x - r0.y;
        float cpd = r1.x + r1.y, cmd = r1.x - r1.y;
        ll.x = (apb + cpd) * 0.5f;  lh.x = (apb - cpd) * 0.5f;
        hl.x = (amb + cmd) * 0.5f;  hh.x = (amb - cmd) * 0.5f;
    }
    {
        float apb = r0.z + r0.w, amb = r0.z - r0.w;
        float cpd = r1.z + r1.w, cmd = r1.z - r1.w;
        ll.y = (apb + cpd) * 0.5f;  lh.y = (apb - cpd) * 0.5f;
        hl.y = (amb + cmd) * 0.5f;  hh.y = (amb - cmd) * 0.5f;
    }

    // Output offset within a plane (floats): (bc, ho, 2*wq)
    unsigned o = (bc * H_OUT + ho) * W_OUT + 2u * wq;
    stcs2(out + 0u * PLANE + o, ll);
    stcs2(out + 1u * PLANE + o, lh);
    stcs2(out + 2u * PLANE + o, hl);
    stcs2(out + 3u * PLANE + o, hh);
}

extern "C" void kernel_launch(void* const* d_in, const int* in_sizes, int n_in,
                              void* d_out, int out_size)
{
    const float4* x = (const float4*)d_in[0];
    float* out = (float*)d_out;

    const int threads = 256;
    const int blocks = (int)(TOTAL_PAIRS / threads);   // 32768, exact
    fast_dwt_kernel<<<blocks, threads>>>(x, out);
}

// round 12
// speedup vs baseline: 1.0027x; 1.0008x over previous
#include <cuda_runtime.h>
#include <cstdint>

// Input:  x  (4, 64, 512, 512) fp32  -> flatten (BC=256, 512, 512)
// Output: [ll | lh | hl | hh], each (256, 256, 256) fp32, concatenated.
//
// Single-level 2x2 Haar DWT, pure streaming kernel (R3 shape; block=128
// closes the block-size axis: 128/256/512 all measured). Each thread reads
// one float4 from rows 2h and 2h+1 (two 2x2 blocks) and writes a float2
// into each of the 4 output planes. Streaming cache hints both directions,
// exact grid, power-of-two index math.
//
// Roofline status (11 rounds): 512 MiB total traffic — algorithmic
// minimum, fully coalesced — pinned at the sm_103a path-independent
// LTS/HBM streaming cap (~6.3-6.5 TB/s run-to-run DVFS wander). All
// structural levers (ILP, burst shaping, cache policy, smem staging,
// persistent grids, block size) measured non-binding.

static constexpr int BC    = 256;          // 4 * 64
static constexpr int W_IN  = 512;
static constexpr int H_OUT = 256;
static constexpr int W_OUT = 256;
static constexpr int PLANE = BC * H_OUT * W_OUT;        // 16,777,216 elems/plane
static constexpr int W4    = W_IN / 4;                  // 128 float4 per input row
static constexpr long long TOTAL_PAIRS = (long long)BC * H_OUT * (W_OUT / 2); // 8,388,608
static constexpr int THREADS = 128;

__device__ __forceinline__ float4 ldcs4(const float4* p) {
    float4 v;
    asm volatile("ld.global.cs.v4.f32 {%0,%1,%2,%3}, [%4];"
                 : "=f"(v.x), "=f"(v.y), "=f"(v.z), "=f"(v.w) : "l"(p));
    return v;
}

__device__ __forceinline__ void stcs2(float* p, float2 v) {
    asm volatile("st.global.cs.v2.f32 [%0], {%1,%2};"
                 :: "l"(p), "f"(v.x), "f"(v.y) : "memory");
}

__global__ void __launch_bounds__(THREADS) fast_dwt_kernel(
    const float4* __restrict__ x,
    float* __restrict__ out)
{
    // Exact grid: no bounds check needed.
    unsigned idx = blockIdx.x * blockDim.x + threadIdx.x;   // < 8,388,608

    unsigned wq = idx & (W4 - 1);          // quad within row (W4=128, pow2)
    unsigned t  = idx >> 7;
    unsigned ho = t & (H_OUT - 1);         // 256, pow2
    unsigned bc = t >> 8;

    // Input rows 2*ho and 2*ho+1, as float4 indices.
    unsigned row0 = (bc * 512u + 2u * ho) * W4;
    float4 r0 = ldcs4(x + row0 + wq);
    float4 r1 = ldcs4(x + row0 + W4 + wq);

    float2 ll, lh, hl, hh;
    {
        float apb = r0.x + r0.y, amb = r0.x - r0.y;
        float cpd = r1.x + r1.y, cmd = r1.x - r1.y;
        ll.x = (apb + cpd) * 0.5f;  lh.x = (apb - cpd) * 0.5f;
        hl.x = (amb + cmd) * 0.5f;  hh.x = (amb - cmd) * 0.5f;
    }
    {
        float apb = r0.z + r0.w, amb = r0.z - r0.w;
        float cpd = r1.z + r1.w, cmd = r1.z - r1.w;
        ll.y = (apb + cpd) * 0.5f;  lh.y = (apb - cpd) * 0.5f;
        hl.y = (amb + cmd) * 0.5f;  hh.y = (amb - cmd) * 0.5f;
    }

    // Output offset within a plane (floats): (bc, ho, 2*wq)
    unsigned o = (bc * H_OUT + ho) * W_OUT + 2u * wq;
    stcs2(out + 0u * PLANE + o, ll);
    stcs2(out + 1u * PLANE + o, lh);
    stcs2(out + 2u * PLANE + o, hl);
    stcs2(out + 3u * PLANE + o, hh);
}

extern "C" void kernel_launch(void* const* d_in, const int* in_sizes, int n_in,
                              void* d_out, int out_size)
{
    const float4* x = (const float4*)d_in[0];
    float* out = (float*)d_out;

    const int blocks = (int)(TOTAL_PAIRS / THREADS);   // 65536, exact
    fast_dwt_kernel<<<blocks, THREADS>>>(x, out);
}

// round 13
// speedup vs baseline: 1.0055x; 1.0027x over previous
#include <cuda_runtime.h>
#include <cstdint>

// Input:  x  (4, 64, 512, 512) fp32  -> flatten (BC=256, 512, 512)
// Output: [ll | lh | hl | hh], each (256, 256, 256) fp32, concatenated.
//
// SESSION FINAL. Single-level 2x2 Haar DWT, pure streaming kernel.
// Each thread reads one float4 from rows 2h and 2h+1 (two 2x2 blocks) and
// writes a float2 into each of the 4 output planes. Streaming cache hints
// both directions, exact grid (no tail branch), pow2 index math, 128
// thr/CTA (best measured kernel time 74.6 us, DRAM 82.1%).
//
// Roofline status (12 rounds, full variant matrix): 512 MiB total traffic
// — algorithmic minimum, fully coalesced — pinned at the sm_103a
// path-independent LTS/HBM streaming cap (~6.3-6.5 TB/s run-to-run DVFS
// wander). ILP, store burst shaping, cache policy, smem staging,
// persistent grids, block size 128/256/512: all measured non-binding.

static constexpr int BC    = 256;          // 4 * 64
static constexpr int W_IN  = 512;
static constexpr int H_OUT = 256;
static constexpr int W_OUT = 256;
static constexpr int PLANE = BC * H_OUT * W_OUT;        // 16,777,216 elems/plane
static constexpr int W4    = W_IN / 4;                  // 128 float4 per input row
static constexpr long long TOTAL_PAIRS = (long long)BC * H_OUT * (W_OUT / 2); // 8,388,608
static constexpr int THREADS = 128;

__device__ __forceinline__ float4 ldcs4(const float4* p) {
    float4 v;
    asm volatile("ld.global.cs.v4.f32 {%0,%1,%2,%3}, [%4];"
                 : "=f"(v.x), "=f"(v.y), "=f"(v.z), "=f"(v.w) : "l"(p));
    return v;
}

__device__ __forceinline__ void stcs2(float* p, float2 v) {
    asm volatile("st.global.cs.v2.f32 [%0], {%1,%2};"
                 :: "l"(p), "f"(v.x), "f"(v.y) : "memory");
}

__global__ void __launch_bounds__(THREADS) fast_dwt_kernel(
    const float4* __restrict__ x,
    float* __restrict__ out)
{
    // Exact grid: no bounds check needed.
    unsigned idx = blockIdx.x * blockDim.x + threadIdx.x;   // < 8,388,608

    unsigned wq = idx & (W4 - 1);          // quad within row (W4=128, pow2)
    unsigned t  = idx >> 7;
    unsigned ho = t & (H_OUT - 1);         // 256, pow2
    unsigned bc = t >> 8;

    // Input rows 2*ho and 2*ho+1, as float4 indices.
    unsigned row0 = (bc * 512u + 2u * ho) * W4;
    float4 r0 = ldcs4(x + row0 + wq);
    float4 r1 = ldcs4(x + row0 + W4 + wq);

    float2 ll, lh, hl, hh;
    {
        float apb = r0.x + r0.y, amb = r0.x - r0.y;
        float cpd = r1.x + r1.y, cmd = r1.x - r1.y;
        ll.x = (apb + cpd) * 0.5f;  lh.x = (apb - cpd) * 0.5f;
        hl.x = (amb + cmd) * 0.5f;  hh.x = (amb - cmd) * 0.5f;
    }
    {
        float apb = r0.z + r0.w, amb = r0.z - r0.w;
        float cpd = r1.z + r1.w, cmd = r1.z - r1.w;
        ll.y = (apb + cpd) * 0.5f;  lh.y = (apb - cpd) * 0.5f;
        hl.y = (amb + cmd) * 0.5f;  hh.y = (amb - cmd) * 0.5f;
    }

    // Output offset within a plane (floats): (bc, ho, 2*wq)
    unsigned o = (bc * H_OUT + ho) * W_OUT + 2u * wq;
    stcs2(out + 0u * PLANE + o, ll);
    stcs2(out + 1u * PLANE + o, lh);
    stcs2(out + 2u * PLANE + o, hl);
    stcs2(out + 3u * PLANE + o, hh);
}

extern "C" void kernel_launch(void* const* d_in, const int* in_sizes, int n_in,
                              void* d_out, int out_size)
{
    const float4* x = (const float4*)d_in[0];
    float* out = (float*)d_out;

    const int blocks = (int)(TOTAL_PAIRS / THREADS);   // 65536, exact
    fast_dwt_kernel<<<blocks, THREADS>>>(x, out);
}